// round 1
// baseline (speedup 1.0000x reference)
#include <cuda_runtime.h>
#include <math.h>

#define NMAT 256
#define D 64
#define DD 4096
#define SLD 68            // smem row stride in floats (16B-aligned float4 rows)
#define NC 32             // Chebyshev coefficients (degree 31)
#define LOG_LO 0.45
#define LOG_HI 5.6

// ---------------- device scratch (static, allocation-free) ----------------
__device__ double g_cheb[NC];
__device__ float  g_logX[NMAT * DD];
__device__ float  g_Y[NMAT * DD];
__device__ float  g_W[NMAT * NMAT];
__device__ float  g_gramP[8 * NMAT * NMAT];
__device__ float  g_sq[NMAT], g_s[NMAT], g_rowS[NMAT], g_colS[NMAT];

// ---------------- Chebyshev coefficients for log on [LOG_LO, LOG_HI] ------
__global__ void cheb_kernel() {
    int k = threadIdx.x;
    if (k >= NC) return;
    const int M = 512;
    const double PI = 3.14159265358979323846;
    double mid = 0.5 * (LOG_LO + LOG_HI), half = 0.5 * (LOG_HI - LOG_LO);
    double acc = 0.0;
    for (int j = 0; j < M; j++) {
        double th = PI * (j + 0.5) / M;
        acc += log(mid + half * cos(th)) * cos((double)k * th);
    }
    g_cheb[k] = 2.0 * acc / M;
}

// ---------------- 64x64 smem matmul: acc += A * B, 16x16 threads, 4x4 tile -
__device__ __forceinline__ void mm64(const float* __restrict__ A,
                                     const float* __restrict__ B,
                                     float acc[4][4], int tx, int ty) {
#pragma unroll 8
    for (int kk = 0; kk < D; kk++) {
        float a0 = A[(4 * ty + 0) * SLD + kk];
        float a1 = A[(4 * ty + 1) * SLD + kk];
        float a2 = A[(4 * ty + 2) * SLD + kk];
        float a3 = A[(4 * ty + 3) * SLD + kk];
        float4 b = *(const float4*)(B + kk * SLD + 4 * tx);
        acc[0][0] += a0 * b.x; acc[0][1] += a0 * b.y; acc[0][2] += a0 * b.z; acc[0][3] += a0 * b.w;
        acc[1][0] += a1 * b.x; acc[1][1] += a1 * b.y; acc[1][2] += a1 * b.z; acc[1][3] += a1 * b.w;
        acc[2][0] += a2 * b.x; acc[2][1] += a2 * b.y; acc[2][2] += a2 * b.z; acc[2][3] += a2 * b.w;
        acc[3][0] += a3 * b.x; acc[3][1] += a3 * b.y; acc[3][2] += a3 * b.z; acc[3][3] += a3 * b.w;
    }
}

// ---------------- matrix log via Clenshaw (one block per matrix) ----------
__global__ void matlog_kernel(const float* __restrict__ X) {
    extern __shared__ float sm[];
    float* T    = sm;
    float* buf0 = sm + 1 * D * SLD;
    float* buf1 = sm + 2 * D * SLD;
    float* buf2 = sm + 3 * D * SLD;
    int mat = blockIdx.x, t = threadIdx.x;
    int tx = t & 15, ty = t >> 4;
    const float inv = (float)(2.0 / (LOG_HI - LOG_LO));
    const float sh  = (float)((LOG_HI + LOG_LO) / (LOG_HI - LOG_LO));
#pragma unroll
    for (int q = 0; q < 16; q++) {
        int l = t + 256 * q;
        int r = l >> 6, c = l & 63;
        float v = X[mat * DD + l] * inv;
        if (r == c) v -= sh;
        T[r * SLD + c]    = v;
        buf0[r * SLD + c] = 0.f;
        buf1[r * SLD + c] = 0.f;
    }
    __syncthreads();
    float* cur = buf0;   // b_{k+1}
    float* prv = buf1;   // b_{k+2}
    float* nxt = buf2;
    for (int k = NC - 1; k >= 1; k--) {
        float ck = (float)g_cheb[k];
        float acc[4][4] = {};
        mm64(T, cur, acc, tx, ty);
#pragma unroll
        for (int i = 0; i < 4; i++) {
            int r = 4 * ty + i;
#pragma unroll
            for (int j = 0; j < 4; j++) {
                int c = 4 * tx + j;
                float v = 2.f * acc[i][j] - prv[r * SLD + c];
                if (r == c) v += ck;
                nxt[r * SLD + c] = v;
            }
        }
        __syncthreads();
        float* tmp = prv; prv = cur; cur = nxt; nxt = tmp;
    }
    // result = T*b1 - b2 + (c0/2) I ; fused epilogue: per-matrix sum & sumsq
    float c0h = 0.5f * (float)g_cheb[0];
    float acc[4][4] = {};
    mm64(T, cur, acc, tx, ty);
    float ls = 0.f, lq = 0.f;
#pragma unroll
    for (int i = 0; i < 4; i++) {
        int r = 4 * ty + i;
#pragma unroll
        for (int j = 0; j < 4; j++) {
            int c = 4 * tx + j;
            float v = acc[i][j] - prv[r * SLD + c];
            if (r == c) v += c0h;
            g_logX[mat * DD + r * 64 + c] = v;
            ls += v; lq += v * v;
        }
    }
    __syncthreads();
    float* red = nxt;          // scratch (not cur/prv)
    red[t] = ls; red[256 + t] = lq;
    __syncthreads();
    for (int off = 128; off > 0; off >>= 1) {
        if (t < off) { red[t] += red[t + off]; red[256 + t] += red[256 + t + off]; }
        __syncthreads();
    }
    if (t == 0) { g_s[mat] = red[0]; g_sq[mat] = red[256]; }
}

// ---------------- gram partials: gram = L L^T, K split 8 ways -------------
__global__ void gram_kernel() {
    __shared__ float As[64][33];   // [kk][row]
    __shared__ float Bs[64][33];
    int bi = blockIdx.x, bj = blockIdx.y, bz = blockIdx.z;
    int t = threadIdx.x, tx = t & 15, ty = t >> 4;
    float acc[2][2] = {};
    for (int kc = 0; kc < 512; kc += 64) {
        int kb = bz * 512 + kc;
#pragma unroll
        for (int q = 0; q < 8; q++) {
            int l = t + 256 * q;
            int r = l >> 6, c = l & 63;
            As[c][r] = g_logX[(bi * 32 + r) * DD + kb + c];
            Bs[c][r] = g_logX[(bj * 32 + r) * DD + kb + c];
        }
        __syncthreads();
#pragma unroll 8
        for (int kk = 0; kk < 64; kk++) {
            float a0 = As[kk][2 * ty], a1 = As[kk][2 * ty + 1];
            float b0 = Bs[kk][2 * tx], b1 = Bs[kk][2 * tx + 1];
            acc[0][0] += a0 * b0; acc[0][1] += a0 * b1;
            acc[1][0] += a1 * b0; acc[1][1] += a1 * b1;
        }
        __syncthreads();
    }
#pragma unroll
    for (int a = 0; a < 2; a++)
#pragma unroll
        for (int b = 0; b < 2; b++)
            g_gramP[bz * 65536 + (bi * 32 + 2 * ty + a) * 256 + (bj * 32 + 2 * tx + b)] = acc[a][b];
}

// ---------------- W = exp(-0.5*pds/bw^2) ----------------------------------
__global__ void w_kernel(const float* __restrict__ bwp) {
    int idx = blockIdx.x * 256 + threadIdx.x;
    int i = idx >> 8, j = idx & 255;
    float g = 0.f;
#pragma unroll
    for (int z = 0; z < 8; z++) g += g_gramP[z * 65536 + idx];
    const float eps = 1e-7f;
    float pds = g_sq[i] + g_sq[j] - 2.f * g
              + 2.f * eps * (g_s[j] - g_s[i]) + eps * eps * (float)DD;
    float bw = bwp[0];
    g_W[idx] = expf(-0.5f * pds / (bw * bw));
}

// ---------------- row & column sums of W ----------------------------------
__global__ void rowcol_kernel() {
    __shared__ float sr[256], sc[256];
    int k = blockIdx.x, j = threadIdx.x;
    sr[j] = g_W[k * 256 + j];
    sc[j] = g_W[j * 256 + k];
    __syncthreads();
    for (int off = 128; off > 0; off >>= 1) {
        if (j < off) { sr[j] += sr[j + off]; sc[j] += sc[j + off]; }
        __syncthreads();
    }
    if (j == 0) { g_rowS[k] = sr[0]; g_colS[k] = sc[0]; }
}

// ---------------- Y = logX + M  (fused W^T * L GEMM epilogue) -------------
__global__ void ygemm_kernel() {
    __shared__ float Ws[32][68];
    __shared__ float Ls[32][68];
    int bab = blockIdx.x, bk = blockIdx.y;
    int t = threadIdx.x, tx = t & 15, ty = t >> 4;
    float acc[4][4] = {};
    for (int jc = 0; jc < 256; jc += 32) {
#pragma unroll
        for (int q = 0; q < 8; q++) {
            int l = t + 256 * q;
            int jj = l >> 6, c = l & 63;
            Ws[jj][c] = g_W[(jc + jj) * 256 + bk * 64 + c];
            Ls[jj][c] = g_logX[(jc + jj) * DD + bab * 64 + c];
        }
        __syncthreads();
#pragma unroll 8
        for (int jj = 0; jj < 32; jj++) {
            float a0 = Ws[jj][4 * ty + 0];
            float a1 = Ws[jj][4 * ty + 1];
            float a2 = Ws[jj][4 * ty + 2];
            float a3 = Ws[jj][4 * ty + 3];
            float4 b = *(const float4*)&Ls[jj][4 * tx];
            acc[0][0] += a0 * b.x; acc[0][1] += a0 * b.y; acc[0][2] += a0 * b.z; acc[0][3] += a0 * b.w;
            acc[1][0] += a1 * b.x; acc[1][1] += a1 * b.y; acc[1][2] += a1 * b.z; acc[1][3] += a1 * b.w;
            acc[2][0] += a2 * b.x; acc[2][1] += a2 * b.y; acc[2][2] += a2 * b.z; acc[2][3] += a2 * b.w;
            acc[3][0] += a3 * b.x; acc[3][1] += a3 * b.y; acc[3][2] += a3 * b.z; acc[3][3] += a3 * b.w;
        }
        __syncthreads();
    }
#pragma unroll
    for (int i = 0; i < 4; i++) {
        int k = bk * 64 + 4 * ty + i;
        float rs = g_rowS[k], cs = g_colS[k];
        float alpha = 1.f - cs / rs, beta = 1.f / rs;
#pragma unroll
        for (int j = 0; j < 4; j++) {
            int ab = bab * 64 + 4 * tx + j;
            g_Y[k * DD + ab] = alpha * g_logX[k * DD + ab] + beta * acc[i][j];
        }
    }
}

// ---------------- matrix exp: scaling & squaring + Taylor-8 Horner --------
__global__ void matexp_kernel(float* __restrict__ out) {
    extern __shared__ float sm[];
    float* A  = sm;
    float* R  = sm + 1 * D * SLD;
    float* Tm = sm + 2 * D * SLD;
    int mat = blockIdx.x, t = threadIdx.x;
    int tx = t & 15, ty = t >> 4;
    float lq = 0.f;
#pragma unroll
    for (int q = 0; q < 16; q++) {
        int l = t + 256 * q;
        int r = l >> 6, c = l & 63;
        float v = g_Y[mat * DD + l];
        A[r * SLD + c] = v;
        lq += v * v;
    }
    float* red = R;
    red[t] = lq;
    __syncthreads();
    for (int off = 128; off > 0; off >>= 1) {
        if (t < off) red[t] += red[t + off];
        __syncthreads();
    }
    float fro = sqrtf(red[0]);
    __syncthreads();                 // done reading red before R is reused
    int s = 0;
    while (fro > 0.35f && s < 10) { fro *= 0.5f; s++; }
    float scale = ldexpf(1.f, -s);
    const float cf[9] = {1.f, 1.f, 0.5f, 1.f / 6.f, 1.f / 24.f, 1.f / 120.f,
                         1.f / 720.f, 1.f / 5040.f, 1.f / 40320.f};
#pragma unroll
    for (int q = 0; q < 16; q++) {
        int l = t + 256 * q;
        int r = l >> 6, c = l & 63;
        float a = A[r * SLD + c] * scale;
        A[r * SLD + c] = a;
        R[r * SLD + c] = cf[8] * a + ((r == c) ? cf[7] : 0.f);
    }
    __syncthreads();
    for (int j = 6; j >= 0; j--) {
        float acc[4][4] = {};
        mm64(R, A, acc, tx, ty);
#pragma unroll
        for (int i = 0; i < 4; i++) {
            int r = 4 * ty + i;
#pragma unroll
            for (int jj = 0; jj < 4; jj++) {
                int c = 4 * tx + jj;
                Tm[r * SLD + c] = acc[i][jj] + ((r == c) ? cf[j] : 0.f);
            }
        }
        __syncthreads();
        float* tmp = R; R = Tm; Tm = tmp;
    }
    for (int q2 = 0; q2 < s; q2++) {
        float acc[4][4] = {};
        mm64(R, R, acc, tx, ty);
#pragma unroll
        for (int i = 0; i < 4; i++) {
            int r = 4 * ty + i;
#pragma unroll
            for (int jj = 0; jj < 4; jj++)
                Tm[r * SLD + 4 * tx + jj] = acc[i][jj];
        }
        __syncthreads();
        float* tmp = R; R = Tm; Tm = tmp;
    }
#pragma unroll
    for (int q = 0; q < 16; q++) {
        int l = t + 256 * q;
        int r = l >> 6, c = l & 63;
        out[mat * DD + l] = R[r * SLD + c];
    }
}

// ---------------- launch ---------------------------------------------------
extern "C" void kernel_launch(void* const* d_in, const int* in_sizes, int n_in,
                              void* d_out, int out_size) {
    const float* X  = (const float*)d_in[0];
    const float* bw = (const float*)d_in[1];
    for (int i = 0; i < n_in; i++) {
        if (in_sizes[i] == NMAT * DD) X = (const float*)d_in[i];
        else if (in_sizes[i] == 1)    bw = (const float*)d_in[i];
    }
    cudaFuncSetAttribute(matlog_kernel, cudaFuncAttributeMaxDynamicSharedMemorySize,
                         4 * D * SLD * (int)sizeof(float));
    cudaFuncSetAttribute(matexp_kernel, cudaFuncAttributeMaxDynamicSharedMemorySize,
                         3 * D * SLD * (int)sizeof(float));

    cheb_kernel<<<1, 32>>>();
    matlog_kernel<<<NMAT, 256, 4 * D * SLD * sizeof(float)>>>(X);
    gram_kernel<<<dim3(8, 8, 8), 256>>>();
    w_kernel<<<(NMAT * NMAT) / 256, 256>>>(bw);
    rowcol_kernel<<<NMAT, 256>>>();
    ygemm_kernel<<<dim3(64, 4), 256>>>();
    matexp_kernel<<<NMAT, 256, 3 * D * SLD * sizeof(float)>>>((float*)d_out);
}

// round 2
// speedup vs baseline: 9.8616x; 9.8616x over previous
#include <cuda_runtime.h>
#include <math.h>

#define NMAT 256
#define D 64
#define DD 4096
#define SLD 68            // smem row stride in floats (16B aligned, 68%4==0)
#define LOG_LO 0.45
#define LOG_HI 5.6

// ---------------- device scratch (static, allocation-free) ----------------
__device__ float g_cc[4][8];      // grouped Chebyshev-PS coefficients
__device__ float g_logX[NMAT * DD];
__device__ float g_Y[NMAT * DD];
__device__ float g_W[NMAT * NMAT];
__device__ float g_gramP[8 * NMAT * NMAT];
__device__ float g_sq[NMAT], g_s[NMAT], g_rowS[NMAT], g_colS[NMAT];

// ---- closed-form Chebyshev coeffs of log on [LOG_LO,LOG_HI], grouped -----
// log(mid + half*x) = log(mid) - log(1+t^2) - 2*sum_k (t^k/k) T_k(x),
// t = (sqrt(1-g^2)-1)/g, g = half/mid.  Degree 31, grouped for PS with s=8:
// p = S0 + T8*I1 + T16*I2 + T24*I3 via T_{8q+r} = 2 T_{8q} T_r - T_{8q-r}.
__global__ void cheb_kernel() {
    if (threadIdx.x != 0) return;
    double mid = 0.5 * (LOG_HI + LOG_LO), half = 0.5 * (LOG_HI - LOG_LO);
    double gam = half / mid;
    double tt = (sqrt(1.0 - gam * gam) - 1.0) / gam;   // |tt|<1, negative
    double g[4][8];
    g[0][0] = log(mid) - log(1.0 + tt * tt);
    double tp = tt;
    for (int k = 1; k < 32; k++) {
        g[k >> 3][k & 7] = -2.0 * tp / (double)k;
        tp *= tt;
    }
    for (int q = 3; q >= 1; q--)
        for (int r = 1; r < 8; r++)
            g[q - 1][8 - r] -= g[q][r];
    for (int r = 0; r < 8; r++) g_cc[0][r] = (float)g[0][r];
    for (int q = 1; q < 4; q++) {
        g_cc[q][0] = (float)g[q][0];
        for (int r = 1; r < 8; r++) g_cc[q][r] = (float)(2.0 * g[q][r]);
    }
}

// ------- 64x64 smem matmul: acc += A*B, 16x16 threads, 4x4 tile -----------
__device__ __forceinline__ void mm64(const float* __restrict__ A,
                                     const float* __restrict__ B,
                                     float acc[4][4], int tx, int ty) {
    const float* A0 = A + (4 * ty) * SLD;
#pragma unroll 2
    for (int k4 = 0; k4 < D; k4 += 4) {
        float ar[4][4];
#pragma unroll
        for (int i = 0; i < 4; i++) {
            float4 a = *(const float4*)(A0 + i * SLD + k4);
            ar[i][0] = a.x; ar[i][1] = a.y; ar[i][2] = a.z; ar[i][3] = a.w;
        }
#pragma unroll
        for (int kk = 0; kk < 4; kk++) {
            float4 b = *(const float4*)(B + (k4 + kk) * SLD + 4 * tx);
#pragma unroll
            for (int i = 0; i < 4; i++) {
                acc[i][0] += ar[i][kk] * b.x;
                acc[i][1] += ar[i][kk] * b.y;
                acc[i][2] += ar[i][kk] * b.z;
                acc[i][3] += ar[i][kk] * b.w;
            }
        }
    }
}

// ---------------- matrix log via Chebyshev-PS (12 matmuls) ----------------
__global__ void __launch_bounds__(256, 2) matlog_kernel(const float* __restrict__ X) {
    extern __shared__ float sm[];
    float* bufA = sm;
    float* b1   = sm + D * SLD;
    float* b2   = sm + 2 * D * SLD;
    int mat = blockIdx.x, t = threadIdx.x;
    int tx = t & 15, ty = t >> 4;
    const float inv = (float)(2.0 / (LOG_HI - LOG_LO));
    const float sh  = (float)((LOG_HI + LOG_LO) / (LOG_HI - LOG_LO));

#pragma unroll
    for (int q = 0; q < 16; q++) {
        int l = t + 256 * q;
        int r = l >> 6, c = l & 63;
        float v = X[mat * DD + l] * inv - ((r == c) ? sh : 0.f);
        bufA[r * SLD + c] = v;
    }
    __syncthreads();

    float RES[4][4], I1[4][4], I2[4][4], I3[4][4];
    {
        float c00 = g_cc[0][0], c01 = g_cc[0][1];
        float c10 = g_cc[1][0], c11 = g_cc[1][1];
        float c20 = g_cc[2][0], c21 = g_cc[2][1];
        float c30 = g_cc[3][0], c31 = g_cc[3][1];
#pragma unroll
        for (int i = 0; i < 4; i++) {
            int r = 4 * ty + i;
#pragma unroll
            for (int j = 0; j < 4; j++) {
                int c = 4 * tx + j;
                float a = bufA[r * SLD + c];
                float dg = (r == c) ? 1.f : 0.f;
                RES[i][j] = c00 * dg + c01 * a;
                I1[i][j]  = c10 * dg + c11 * a;
                I2[i][j]  = c20 * dg + c21 * a;
                I3[i][j]  = c30 * dg + c31 * a;
            }
        }
    }
    // T2 = 2*A*A - I  -> b1
    {
        float acc[4][4] = {};
        mm64(bufA, bufA, acc, tx, ty);
        float w0 = g_cc[0][2], w1 = g_cc[1][2], w2 = g_cc[2][2], w3 = g_cc[3][2];
#pragma unroll
        for (int i = 0; i < 4; i++) { int r = 4 * ty + i;
#pragma unroll
            for (int j = 0; j < 4; j++) { int c = 4 * tx + j;
                float v = 2.f * acc[i][j] - ((r == c) ? 1.f : 0.f);
                b1[r * SLD + c] = v;
                RES[i][j] += w0 * v; I1[i][j] += w1 * v;
                I2[i][j] += w2 * v;  I3[i][j] += w3 * v;
            } }
        __syncthreads();
    }
    // T3 = 2*A*T2 - A -> b2
    {
        float acc[4][4] = {};
        mm64(bufA, b1, acc, tx, ty);
        float w0 = g_cc[0][3], w1 = g_cc[1][3], w2 = g_cc[2][3], w3 = g_cc[3][3];
#pragma unroll
        for (int i = 0; i < 4; i++) { int r = 4 * ty + i;
#pragma unroll
            for (int j = 0; j < 4; j++) { int c = 4 * tx + j;
                float v = 2.f * acc[i][j] - bufA[r * SLD + c];
                b2[r * SLD + c] = v;
                RES[i][j] += w0 * v; I1[i][j] += w1 * v;
                I2[i][j] += w2 * v;  I3[i][j] += w3 * v;
            } }
        __syncthreads();
    }
    // T4..T8: T_k = 2*A*T_{k-1} - T_{k-2}, in-place over T_{k-2}
    {
        float* dst = b1; float* src = b2;
        for (int k = 4; k <= 8; k++) {
            float acc[4][4] = {};
            mm64(bufA, src, acc, tx, ty);
            float w0 = 0.f, w1 = 0.f, w2 = 0.f, w3 = 0.f;
            if (k < 8) { w0 = g_cc[0][k]; w1 = g_cc[1][k]; w2 = g_cc[2][k]; w3 = g_cc[3][k]; }
#pragma unroll
            for (int i = 0; i < 4; i++) { int r = 4 * ty + i;
#pragma unroll
                for (int j = 0; j < 4; j++) { int c = 4 * tx + j;
                    float v = 2.f * acc[i][j] - dst[r * SLD + c];
                    dst[r * SLD + c] = v;
                    RES[i][j] += w0 * v; I1[i][j] += w1 * v;
                    I2[i][j] += w2 * v;  I3[i][j] += w3 * v;
                } }
            __syncthreads();
            float* tmp = dst; dst = src; src = tmp;
        }
    }
    // now: b1 = T8, b2 = T7 (dead), bufA = A (dead)
    // dump I1 -> b2, RES += T8*I1
#pragma unroll
    for (int i = 0; i < 4; i++)
#pragma unroll
        for (int j = 0; j < 4; j++)
            b2[(4 * ty + i) * SLD + 4 * tx + j] = I1[i][j];
    __syncthreads();
    {
        float acc[4][4] = {};
        mm64(b1, b2, acc, tx, ty);
#pragma unroll
        for (int i = 0; i < 4; i++)
#pragma unroll
            for (int j = 0; j < 4; j++) RES[i][j] += acc[i][j];
    }
    // T16 = 2*T8*T8 - I -> bufA
    {
        float acc[4][4] = {};
        mm64(b1, b1, acc, tx, ty);
#pragma unroll
        for (int i = 0; i < 4; i++) { int r = 4 * ty + i;
#pragma unroll
            for (int j = 0; j < 4; j++) { int c = 4 * tx + j;
                bufA[r * SLD + c] = 2.f * acc[i][j] - ((r == c) ? 1.f : 0.f);
            } }
    }
    __syncthreads();
    // dump I2 -> b2 (I1 dead), RES += T16*I2
#pragma unroll
    for (int i = 0; i < 4; i++)
#pragma unroll
        for (int j = 0; j < 4; j++)
            b2[(4 * ty + i) * SLD + 4 * tx + j] = I2[i][j];
    __syncthreads();
    {
        float acc[4][4] = {};
        mm64(bufA, b2, acc, tx, ty);
#pragma unroll
        for (int i = 0; i < 4; i++)
#pragma unroll
            for (int j = 0; j < 4; j++) RES[i][j] += acc[i][j];
    }
    // T24 = 2*T16*T8 - T8 -> b2
    {
        float acc[4][4] = {};
        mm64(bufA, b1, acc, tx, ty);
        __syncthreads();   // all reads of b2 (I2) and b1 done
#pragma unroll
        for (int i = 0; i < 4; i++) { int r = 4 * ty + i;
#pragma unroll
            for (int j = 0; j < 4; j++) { int c = 4 * tx + j;
                b2[r * SLD + c] = 2.f * acc[i][j] - b1[r * SLD + c];
            } }
    }
    __syncthreads();
    // dump I3 -> b1 (T8 dead), RES += T24*I3
#pragma unroll
    for (int i = 0; i < 4; i++)
#pragma unroll
        for (int j = 0; j < 4; j++)
            b1[(4 * ty + i) * SLD + 4 * tx + j] = I3[i][j];
    __syncthreads();
    {
        float acc[4][4] = {};
        mm64(b2, b1, acc, tx, ty);
#pragma unroll
        for (int i = 0; i < 4; i++)
#pragma unroll
            for (int j = 0; j < 4; j++) RES[i][j] += acc[i][j];
    }
    // output + per-matrix sum / sumsq
    float ls = 0.f, lq = 0.f;
#pragma unroll
    for (int i = 0; i < 4; i++) { int r = 4 * ty + i;
#pragma unroll
        for (int j = 0; j < 4; j++) { int c = 4 * tx + j;
            float v = RES[i][j];
            g_logX[mat * DD + r * 64 + c] = v;
            ls += v; lq += v * v;
        } }
    __syncthreads();
    b1[t] = ls; b1[256 + t] = lq;
    __syncthreads();
    for (int off = 128; off > 0; off >>= 1) {
        if (t < off) { b1[t] += b1[t + off]; b1[256 + t] += b1[256 + t + off]; }
        __syncthreads();
    }
    if (t == 0) { g_s[mat] = b1[0]; g_sq[mat] = b1[256]; }
}

// ---------------- gram partials: gram = L L^T, K split 8 ways -------------
__global__ void gram_kernel() {
    __shared__ float As[64][33];
    __shared__ float Bs[64][33];
    int bi = blockIdx.x, bj = blockIdx.y, bz = blockIdx.z;
    int t = threadIdx.x, tx = t & 15, ty = t >> 4;
    float acc[2][2] = {};
    for (int kc = 0; kc < 512; kc += 64) {
        int kb = bz * 512 + kc;
#pragma unroll
        for (int q = 0; q < 8; q++) {
            int l = t + 256 * q;
            int r = l >> 6, c = l & 63;
            As[c][r] = g_logX[(bi * 32 + r) * DD + kb + c];
            Bs[c][r] = g_logX[(bj * 32 + r) * DD + kb + c];
        }
        __syncthreads();
#pragma unroll 8
        for (int kk = 0; kk < 64; kk++) {
            float a0 = As[kk][2 * ty], a1 = As[kk][2 * ty + 1];
            float b0 = Bs[kk][2 * tx], b1 = Bs[kk][2 * tx + 1];
            acc[0][0] += a0 * b0; acc[0][1] += a0 * b1;
            acc[1][0] += a1 * b0; acc[1][1] += a1 * b1;
        }
        __syncthreads();
    }
#pragma unroll
    for (int a = 0; a < 2; a++)
#pragma unroll
        for (int b = 0; b < 2; b++)
            g_gramP[bz * 65536 + (bi * 32 + 2 * ty + a) * 256 + (bj * 32 + 2 * tx + b)] = acc[a][b];
}

// ---------------- W = exp(-0.5*pds/bw^2) ----------------------------------
__global__ void w_kernel(const float* __restrict__ bwp) {
    int idx = blockIdx.x * 256 + threadIdx.x;
    int i = idx >> 8, j = idx & 255;
    float g = 0.f;
#pragma unroll
    for (int z = 0; z < 8; z++) g += g_gramP[z * 65536 + idx];
    const float eps = 1e-7f;
    float pds = g_sq[i] + g_sq[j] - 2.f * g
              + 2.f * eps * (g_s[j] - g_s[i]) + eps * eps * (float)DD;
    float bw = bwp[0];
    g_W[idx] = expf(-0.5f * pds / (bw * bw));
}

// ---------------- row & column sums of W ----------------------------------
__global__ void rowcol_kernel() {
    __shared__ float sr[256], sc[256];
    int k = blockIdx.x, j = threadIdx.x;
    sr[j] = g_W[k * 256 + j];
    sc[j] = g_W[j * 256 + k];
    __syncthreads();
    for (int off = 128; off > 0; off >>= 1) {
        if (j < off) { sr[j] += sr[j + off]; sc[j] += sc[j + off]; }
        __syncthreads();
    }
    if (j == 0) { g_rowS[k] = sr[0]; g_colS[k] = sc[0]; }
}

// ---------------- Y = logX + M  (fused W^T * L GEMM epilogue) -------------
__global__ void ygemm_kernel() {
    __shared__ float Ws[32][68];
    __shared__ float Ls[32][68];
    int bab = blockIdx.x, bk = blockIdx.y;
    int t = threadIdx.x, tx = t & 15, ty = t >> 4;
    float acc[4][4] = {};
    for (int jc = 0; jc < 256; jc += 32) {
#pragma unroll
        for (int q = 0; q < 8; q++) {
            int l = t + 256 * q;
            int jj = l >> 6, c = l & 63;
            Ws[jj][c] = g_W[(jc + jj) * 256 + bk * 64 + c];
            Ls[jj][c] = g_logX[(jc + jj) * DD + bab * 64 + c];
        }
        __syncthreads();
#pragma unroll 8
        for (int jj = 0; jj < 32; jj++) {
            float a0 = Ws[jj][4 * ty + 0];
            float a1 = Ws[jj][4 * ty + 1];
            float a2 = Ws[jj][4 * ty + 2];
            float a3 = Ws[jj][4 * ty + 3];
            float4 b = *(const float4*)&Ls[jj][4 * tx];
            acc[0][0] += a0 * b.x; acc[0][1] += a0 * b.y; acc[0][2] += a0 * b.z; acc[0][3] += a0 * b.w;
            acc[1][0] += a1 * b.x; acc[1][1] += a1 * b.y; acc[1][2] += a1 * b.z; acc[1][3] += a1 * b.w;
            acc[2][0] += a2 * b.x; acc[2][1] += a2 * b.y; acc[2][2] += a2 * b.z; acc[2][3] += a2 * b.w;
            acc[3][0] += a3 * b.x; acc[3][1] += a3 * b.y; acc[3][2] += a3 * b.z; acc[3][3] += a3 * b.w;
        }
        __syncthreads();
    }
#pragma unroll
    for (int i = 0; i < 4; i++) {
        int k = bk * 64 + 4 * ty + i;
        float rs = g_rowS[k], cs = g_colS[k];
        float alpha = 1.f - cs / rs, beta = 1.f / rs;
#pragma unroll
        for (int j = 0; j < 4; j++) {
            int ab = bab * 64 + 4 * tx + j;
            g_Y[k * DD + ab] = alpha * g_logX[k * DD + ab] + beta * acc[i][j];
        }
    }
}

// --------- matrix exp: scaling & squaring + Taylor-8 via PS (4+s mms) -----
__global__ void __launch_bounds__(256, 2) matexp_kernel(float* __restrict__ out) {
    extern __shared__ float sm[];
    float* bufA = sm;
    float* b1   = sm + D * SLD;
    float* b2   = sm + 2 * D * SLD;
    int mat = blockIdx.x, t = threadIdx.x;
    int tx = t & 15, ty = t >> 4;
    float lq = 0.f;
#pragma unroll
    for (int q = 0; q < 16; q++) {
        int l = t + 256 * q;
        int r = l >> 6, c = l & 63;
        float v = g_Y[mat * DD + l];
        bufA[r * SLD + c] = v;
        lq += v * v;
    }
    b1[t] = lq;
    __syncthreads();
    for (int off = 128; off > 0; off >>= 1) {
        if (t < off) b1[t] += b1[t + off];
        __syncthreads();
    }
    float fro = sqrtf(b1[0]);
    __syncthreads();
    int s = 0;
    while (fro > 0.5f && s < 12) { fro *= 0.5f; s++; }
    float scale = ldexpf(1.f, -s);
#pragma unroll
    for (int q = 0; q < 16; q++) {
        int l = t + 256 * q;
        int r = l >> 6, c = l & 63;
        bufA[r * SLD + c] *= scale;
    }
    __syncthreads();

    const float cf[9] = {1.f, 1.f, 0.5f, 1.f / 6.f, 1.f / 24.f, 1.f / 120.f,
                         1.f / 720.f, 1.f / 5040.f, 1.f / 40320.f};
    float Q0[4][4], Q1[4][4], Q2[4][4];
#pragma unroll
    for (int i = 0; i < 4; i++) { int r = 4 * ty + i;
#pragma unroll
        for (int j = 0; j < 4; j++) { int c = 4 * tx + j;
            float a = bufA[r * SLD + c];
            float dg = (r == c) ? 1.f : 0.f;
            Q0[i][j] = cf[0] * dg + cf[1] * a;
            Q1[i][j] = cf[3] * dg + cf[4] * a;
            Q2[i][j] = cf[6] * dg + cf[7] * a;
        } }
    // A2 -> b1
    {
        float acc[4][4] = {};
        mm64(bufA, bufA, acc, tx, ty);
#pragma unroll
        for (int i = 0; i < 4; i++) { int r = 4 * ty + i;
#pragma unroll
            for (int j = 0; j < 4; j++) { int c = 4 * tx + j;
                float v = acc[i][j];
                b1[r * SLD + c] = v;
                Q0[i][j] += cf[2] * v; Q1[i][j] += cf[5] * v; Q2[i][j] += cf[8] * v;
            } }
        __syncthreads();
    }
    // A3 -> b2
    {
        float acc[4][4] = {};
        mm64(bufA, b1, acc, tx, ty);
#pragma unroll
        for (int i = 0; i < 4; i++)
#pragma unroll
            for (int j = 0; j < 4; j++)
                b2[(4 * ty + i) * SLD + 4 * tx + j] = acc[i][j];
        __syncthreads();
    }
    // dump Q2 -> b1 (A2 dead)
#pragma unroll
    for (int i = 0; i < 4; i++)
#pragma unroll
        for (int j = 0; j < 4; j++)
            b1[(4 * ty + i) * SLD + 4 * tx + j] = Q2[i][j];
    __syncthreads();
    // V = A3*Q2 + Q1 -> bufA
    {
        float acc[4][4] = {};
        mm64(b2, b1, acc, tx, ty);
#pragma unroll
        for (int i = 0; i < 4; i++)
#pragma unroll
            for (int j = 0; j < 4; j++)
                bufA[(4 * ty + i) * SLD + 4 * tx + j] = acc[i][j] + Q1[i][j];
        __syncthreads();
    }
    // R = A3*V + Q0 -> b1
    {
        float acc[4][4] = {};
        mm64(b2, bufA, acc, tx, ty);
#pragma unroll
        for (int i = 0; i < 4; i++)
#pragma unroll
            for (int j = 0; j < 4; j++)
                b1[(4 * ty + i) * SLD + 4 * tx + j] = acc[i][j] + Q0[i][j];
        __syncthreads();
    }
    // s squarings
    float* cur = b1; float* nxt = b2;
    for (int it = 0; it < s; it++) {
        float acc[4][4] = {};
        mm64(cur, cur, acc, tx, ty);
#pragma unroll
        for (int i = 0; i < 4; i++)
#pragma unroll
            for (int j = 0; j < 4; j++)
                nxt[(4 * ty + i) * SLD + 4 * tx + j] = acc[i][j];
        __syncthreads();
        float* tmp = cur; cur = nxt; nxt = tmp;
    }
#pragma unroll
    for (int q = 0; q < 16; q++) {
        int l = t + 256 * q;
        int r = l >> 6, c = l & 63;
        out[mat * DD + l] = cur[r * SLD + c];
    }
}

// ---------------- launch ---------------------------------------------------
extern "C" void kernel_launch(void* const* d_in, const int* in_sizes, int n_in,
                              void* d_out, int out_size) {
    const float* X  = (const float*)d_in[0];
    const float* bw = (const float*)d_in[1];
    for (int i = 0; i < n_in; i++) {
        if (in_sizes[i] == NMAT * DD) X = (const float*)d_in[i];
        else if (in_sizes[i] == 1)    bw = (const float*)d_in[i];
    }
    int smem = 3 * D * SLD * (int)sizeof(float);
    cudaFuncSetAttribute(matlog_kernel, cudaFuncAttributeMaxDynamicSharedMemorySize, smem);
    cudaFuncSetAttribute(matexp_kernel, cudaFuncAttributeMaxDynamicSharedMemorySize, smem);

    cheb_kernel<<<1, 32>>>();
    matlog_kernel<<<NMAT, 256, smem>>>(X);
    gram_kernel<<<dim3(8, 8, 8), 256>>>();
    w_kernel<<<(NMAT * NMAT) / 256, 256>>>(bw);
    rowcol_kernel<<<NMAT, 256>>>();
    ygemm_kernel<<<dim3(64, 4), 256>>>();
    matexp_kernel<<<NMAT, 256, smem>>>((float*)d_out);
}

// round 4
// speedup vs baseline: 10.8650x; 1.1017x over previous
#include <cuda_runtime.h>
#include <math.h>

#define NMAT 256
#define D 64
#define DD 4096
#define SLD 68            // smem row stride in floats (16B aligned)
#define LOG_LO 0.45
#define LOG_HI 5.6

typedef unsigned long long ull;

// ---------------- device scratch (static, allocation-free) ----------------
__device__ float g_logX[NMAT * DD];
__device__ float g_Y[NMAT * DD];
__device__ float g_W[NMAT * NMAT];
__device__ float g_gramP[8 * NMAT * NMAT];
__device__ float g_sq[NMAT], g_s[NMAT], g_rowS[NMAT], g_colS[NMAT];

struct CC { float c[4][8]; };   // grouped Chebyshev-PS coefficients (host-computed)

// ---------------- packed f32x2 helpers ------------------------------------
__device__ __forceinline__ ull f2pack(float lo, float hi) {
    ull d; asm("mov.b64 %0, {%1, %2};" : "=l"(d)
               : "r"(__float_as_uint(lo)), "r"(__float_as_uint(hi)));
    return d;
}
__device__ __forceinline__ ull fdup(float x) { return f2pack(x, x); }
__device__ __forceinline__ void f2unpack(ull v, float& lo, float& hi) {
    unsigned a, b; asm("mov.b64 {%0, %1}, %2;" : "=r"(a), "=r"(b) : "l"(v));
    lo = __uint_as_float(a); hi = __uint_as_float(b);
}
__device__ __forceinline__ ull fma2(ull a, ull b, ull c) {
    ull d; asm("fma.rn.f32x2 %0, %1, %2, %3;" : "=l"(d) : "l"(a), "l"(b), "l"(c));
    return d;
}
__device__ __forceinline__ ull add2(ull a, ull b) {
    ull d; asm("add.rn.f32x2 %0, %1, %2;" : "=l"(d) : "l"(a), "l"(b));
    return d;
}
__device__ __forceinline__ ull mul2(ull a, ull b) {
    ull d; asm("mul.rn.f32x2 %0, %1, %2;" : "=l"(d) : "l"(a), "l"(b));
    return d;
}
__device__ __forceinline__ ull neg2(ull a) { return a ^ 0x8000000080000000ULL; }

// diag mask pair for tile element (row r, cols cb+2jp, cb+2jp+1)
__device__ __forceinline__ ull dgp(int r, int cb, int jp) {
    return f2pack((cb + 2 * jp == r) ? 1.f : 0.f, (cb + 2 * jp + 1 == r) ? 1.f : 0.f);
}

// ---- packed k-major matmul: C[4ty+i][4tx+2jp..+1] += sum_k A[k][i]*B[k][j]
// A must be symmetric (read row-k as column) or stored k-major. nk in {32,64}.
__device__ __forceinline__ void mmp(const float* __restrict__ A,
                                    const float* __restrict__ B,
                                    int nk, ull acc[4][2], int tx, int ty) {
    const float* Ak = A + 4 * ty;
    const float* Bk = B + 4 * tx;
#pragma unroll 4
    for (int k = 0; k < nk; k++) {
        float4 a = *(const float4*)Ak;
        ulonglong2 b = *(const ulonglong2*)Bk;
        ull a0 = fdup(a.x), a1 = fdup(a.y), a2 = fdup(a.z), a3 = fdup(a.w);
        acc[0][0] = fma2(a0, b.x, acc[0][0]); acc[0][1] = fma2(a0, b.y, acc[0][1]);
        acc[1][0] = fma2(a1, b.x, acc[1][0]); acc[1][1] = fma2(a1, b.y, acc[1][1]);
        acc[2][0] = fma2(a2, b.x, acc[2][0]); acc[2][1] = fma2(a2, b.y, acc[2][1]);
        acc[3][0] = fma2(a3, b.x, acc[3][0]); acc[3][1] = fma2(a3, b.y, acc[3][1]);
        Ak += SLD; Bk += SLD;
    }
}

#define TOFF(buf, i, jp) ((ull*)((buf) + (4 * ty + (i)) * SLD + cb + 2 * (jp)))

// ---------------- matrix log via Chebyshev-PS (12 packed matmuls) ---------
__global__ void __launch_bounds__(256, 2) matlog_kernel(const float* __restrict__ X, CC cc) {
    extern __shared__ float sm[];
    float* bufA = sm;
    float* b1   = sm + D * SLD;
    float* b2   = sm + 2 * D * SLD;
    int mat = blockIdx.x, t = threadIdx.x;
    int tx = t & 15, ty = t >> 4;
    int cb = 4 * tx;
    const float inv = (float)(2.0 / (LOG_HI - LOG_LO));
    const float sh  = (float)((LOG_HI + LOG_LO) / (LOG_HI - LOG_LO));

#pragma unroll
    for (int q = 0; q < 16; q++) {
        int l = t + 256 * q;
        int r = l >> 6, c = l & 63;
        bufA[r * SLD + c] = X[mat * DD + l] * inv - ((r == c) ? sh : 0.f);
    }
    __syncthreads();

    ull RES[4][2], I1[4][2], I2[4][2], I3[4][2];
    {
        ull c00 = fdup(cc.c[0][0]), c01 = fdup(cc.c[0][1]);
        ull c10 = fdup(cc.c[1][0]), c11 = fdup(cc.c[1][1]);
        ull c20 = fdup(cc.c[2][0]), c21 = fdup(cc.c[2][1]);
        ull c30 = fdup(cc.c[3][0]), c31 = fdup(cc.c[3][1]);
#pragma unroll
        for (int i = 0; i < 4; i++) {
            int r = 4 * ty + i;
#pragma unroll
            for (int jp = 0; jp < 2; jp++) {
                ull a  = *TOFF(bufA, i, jp);
                ull dg = dgp(r, cb, jp);
                RES[i][jp] = fma2(a, c01, mul2(dg, c00));
                I1[i][jp]  = fma2(a, c11, mul2(dg, c10));
                I2[i][jp]  = fma2(a, c21, mul2(dg, c20));
                I3[i][jp]  = fma2(a, c31, mul2(dg, c30));
            }
        }
    }
    // T2 = 2*A*A - I -> b1
    {
        ull acc[4][2] = {}; mmp(bufA, bufA, D, acc, tx, ty);
        ull w0 = fdup(cc.c[0][2]), w1 = fdup(cc.c[1][2]), w2 = fdup(cc.c[2][2]), w3 = fdup(cc.c[3][2]);
#pragma unroll
        for (int i = 0; i < 4; i++) { int r = 4 * ty + i;
#pragma unroll
            for (int jp = 0; jp < 2; jp++) {
                ull v = add2(add2(acc[i][jp], acc[i][jp]), neg2(dgp(r, cb, jp)));
                *TOFF(b1, i, jp) = v;
                RES[i][jp] = fma2(v, w0, RES[i][jp]); I1[i][jp] = fma2(v, w1, I1[i][jp]);
                I2[i][jp]  = fma2(v, w2, I2[i][jp]);  I3[i][jp] = fma2(v, w3, I3[i][jp]);
            } }
        __syncthreads();
    }
    // T3 = 2*A*T2 - A -> b2
    {
        ull acc[4][2] = {}; mmp(bufA, b1, D, acc, tx, ty);
        ull w0 = fdup(cc.c[0][3]), w1 = fdup(cc.c[1][3]), w2 = fdup(cc.c[2][3]), w3 = fdup(cc.c[3][3]);
#pragma unroll
        for (int i = 0; i < 4; i++)
#pragma unroll
            for (int jp = 0; jp < 2; jp++) {
                ull av = *TOFF(bufA, i, jp);
                ull v = add2(add2(acc[i][jp], acc[i][jp]), neg2(av));
                *TOFF(b2, i, jp) = v;
                RES[i][jp] = fma2(v, w0, RES[i][jp]); I1[i][jp] = fma2(v, w1, I1[i][jp]);
                I2[i][jp]  = fma2(v, w2, I2[i][jp]);  I3[i][jp] = fma2(v, w3, I3[i][jp]);
            }
        __syncthreads();
    }
    // T4..T8: T_k = 2*A*T_{k-1} - T_{k-2}, in-place over T_{k-2}
    {
        float* dst = b1; float* src = b2;
        for (int k = 4; k <= 8; k++) {
            ull acc[4][2] = {}; mmp(bufA, src, D, acc, tx, ty);
            float cw0 = (k < 8) ? cc.c[0][k] : 0.f;
            float cw1 = (k < 8) ? cc.c[1][k] : 0.f;
            float cw2 = (k < 8) ? cc.c[2][k] : 0.f;
            float cw3 = (k < 8) ? cc.c[3][k] : 0.f;
            ull w0 = fdup(cw0), w1 = fdup(cw1), w2 = fdup(cw2), w3 = fdup(cw3);
#pragma unroll
            for (int i = 0; i < 4; i++)
#pragma unroll
                for (int jp = 0; jp < 2; jp++) {
                    ull* p = TOFF(dst, i, jp);
                    ull v = add2(add2(acc[i][jp], acc[i][jp]), neg2(*p));
                    *p = v;
                    RES[i][jp] = fma2(v, w0, RES[i][jp]); I1[i][jp] = fma2(v, w1, I1[i][jp]);
                    I2[i][jp]  = fma2(v, w2, I2[i][jp]);  I3[i][jp] = fma2(v, w3, I3[i][jp]);
                }
            __syncthreads();
            float* tmp = dst; dst = src; src = tmp;
        }
    }
    // b1 = T8.  dump I1 -> b2, RES += T8*I1
#pragma unroll
    for (int i = 0; i < 4; i++)
#pragma unroll
        for (int jp = 0; jp < 2; jp++) *TOFF(b2, i, jp) = I1[i][jp];
    __syncthreads();
    {
        ull acc[4][2] = {}; mmp(b1, b2, D, acc, tx, ty);
#pragma unroll
        for (int i = 0; i < 4; i++)
#pragma unroll
            for (int jp = 0; jp < 2; jp++) RES[i][jp] = add2(RES[i][jp], acc[i][jp]);
    }
    // T16 = 2*T8*T8 - I -> bufA
    {
        ull acc[4][2] = {}; mmp(b1, b1, D, acc, tx, ty);
#pragma unroll
        for (int i = 0; i < 4; i++) { int r = 4 * ty + i;
#pragma unroll
            for (int jp = 0; jp < 2; jp++)
                *TOFF(bufA, i, jp) = add2(add2(acc[i][jp], acc[i][jp]), neg2(dgp(r, cb, jp)));
        }
    }
    __syncthreads();
    // dump I2 -> b2, RES += T16*I2
#pragma unroll
    for (int i = 0; i < 4; i++)
#pragma unroll
        for (int jp = 0; jp < 2; jp++) *TOFF(b2, i, jp) = I2[i][jp];
    __syncthreads();
    {
        ull acc[4][2] = {}; mmp(bufA, b2, D, acc, tx, ty);
#pragma unroll
        for (int i = 0; i < 4; i++)
#pragma unroll
            for (int jp = 0; jp < 2; jp++) RES[i][jp] = add2(RES[i][jp], acc[i][jp]);
    }
    // T24 = 2*T16*T8 - T8 -> b2
    {
        ull acc[4][2] = {}; mmp(bufA, b1, D, acc, tx, ty);
        __syncthreads();   // all reads of b2 (I2) and b1 done
#pragma unroll
        for (int i = 0; i < 4; i++)
#pragma unroll
            for (int jp = 0; jp < 2; jp++) {
                ull pv = *TOFF(b1, i, jp);
                *TOFF(b2, i, jp) = add2(add2(acc[i][jp], acc[i][jp]), neg2(pv));
            }
    }
    __syncthreads();
    // dump I3 -> b1, RES += T24*I3
#pragma unroll
    for (int i = 0; i < 4; i++)
#pragma unroll
        for (int jp = 0; jp < 2; jp++) *TOFF(b1, i, jp) = I3[i][jp];
    __syncthreads();
    {
        ull acc[4][2] = {}; mmp(b2, b1, D, acc, tx, ty);
#pragma unroll
        for (int i = 0; i < 4; i++)
#pragma unroll
            for (int jp = 0; jp < 2; jp++) RES[i][jp] = add2(RES[i][jp], acc[i][jp]);
    }
    // output + per-matrix sum / sumsq
    float ls = 0.f, lq = 0.f;
#pragma unroll
    for (int i = 0; i < 4; i++)
#pragma unroll
        for (int jp = 0; jp < 2; jp++) {
            float v0, v1; f2unpack(RES[i][jp], v0, v1);
            ls += v0 + v1; lq += v0 * v0 + v1 * v1;
            *(ull*)(&g_logX[mat * DD + (4 * ty + i) * 64 + cb + 2 * jp]) = RES[i][jp];
        }
    __syncthreads();
    b1[t] = ls; b1[256 + t] = lq;
    __syncthreads();
    for (int off = 128; off > 0; off >>= 1) {
        if (t < off) { b1[t] += b1[t + off]; b1[256 + t] += b1[256 + t + off]; }
        __syncthreads();
    }
    if (t == 0) { g_s[mat] = b1[0]; g_sq[mat] = b1[256]; }
}

// ---------------- gram partials: gram = L L^T, K split 8 ways -------------
__global__ void gram_kernel() {
    __shared__ float As[64][34];   // [kk][row], even stride for 8B loads
    __shared__ float Bs[64][34];
    int bi = blockIdx.x, bj = blockIdx.y, bz = blockIdx.z;
    int t = threadIdx.x, tx = t & 15, ty = t >> 4;
    ull acc[2] = {0ULL, 0ULL};
    for (int kc = 0; kc < 512; kc += 64) {
        int kb = bz * 512 + kc;
#pragma unroll
        for (int q = 0; q < 8; q++) {
            int l = t + 256 * q;
            int r = l >> 6, c = l & 63;
            As[c][r] = g_logX[(bi * 32 + r) * DD + kb + c];
            Bs[c][r] = g_logX[(bj * 32 + r) * DD + kb + c];
        }
        __syncthreads();
#pragma unroll 8
        for (int kk = 0; kk < 64; kk++) {
            float2 av = *(const float2*)&As[kk][2 * ty];
            ull bv = *(const ull*)&Bs[kk][2 * tx];
            acc[0] = fma2(fdup(av.x), bv, acc[0]);
            acc[1] = fma2(fdup(av.y), bv, acc[1]);
        }
        __syncthreads();
    }
#pragma unroll
    for (int a = 0; a < 2; a++)
        *(ull*)&g_gramP[bz * 65536 + (bi * 32 + 2 * ty + a) * 256 + (bj * 32 + 2 * tx)] = acc[a];
}

// ---------------- W = exp(-0.5*pds/bw^2) ----------------------------------
__global__ void w_kernel(const float* __restrict__ bwp) {
    int idx = blockIdx.x * 256 + threadIdx.x;
    int i = idx >> 8, j = idx & 255;
    float g = 0.f;
#pragma unroll
    for (int z = 0; z < 8; z++) g += g_gramP[z * 65536 + idx];
    const float eps = 1e-7f;
    float pds = g_sq[i] + g_sq[j] - 2.f * g
              + 2.f * eps * (g_s[j] - g_s[i]) + eps * eps * (float)DD;
    float bw = bwp[0];
    g_W[idx] = expf(-0.5f * pds / (bw * bw));
}

// ---------------- row & column sums of W ----------------------------------
__global__ void rowcol_kernel() {
    __shared__ float sr[256], sc[256];
    int k = blockIdx.x, j = threadIdx.x;
    sr[j] = g_W[k * 256 + j];
    sc[j] = g_W[j * 256 + k];
    __syncthreads();
    for (int off = 128; off > 0; off >>= 1) {
        if (j < off) { sr[j] += sr[j + off]; sc[j] += sc[j + off]; }
        __syncthreads();
    }
    if (j == 0) { g_rowS[k] = sr[0]; g_colS[k] = sc[0]; }
}

// ---------------- Y = logX + M  (fused W^T * L GEMM epilogue) -------------
__global__ void ygemm_kernel() {
    __shared__ float Ws[32][SLD];
    __shared__ float Ls[32][SLD];
    int bab = blockIdx.x, bk = blockIdx.y;
    int t = threadIdx.x, tx = t & 15, ty = t >> 4;
    int cb = 4 * tx;
    ull acc[4][2] = {};
    for (int jc = 0; jc < 256; jc += 32) {
#pragma unroll
        for (int q = 0; q < 8; q++) {
            int l = t + 256 * q;
            int jj = l >> 6, c = l & 63;
            Ws[jj][c] = g_W[(jc + jj) * 256 + bk * 64 + c];
            Ls[jj][c] = g_logX[(jc + jj) * DD + bab * 64 + c];
        }
        __syncthreads();
        mmp(&Ws[0][0], &Ls[0][0], 32, acc, tx, ty);
        __syncthreads();
    }
#pragma unroll
    for (int i = 0; i < 4; i++) {
        int k = bk * 64 + 4 * ty + i;
        float rs = g_rowS[k], cs = g_colS[k];
        ull al = fdup(1.f - cs / rs), be = fdup(1.f / rs);
#pragma unroll
        for (int jp = 0; jp < 2; jp++) {
            int ab = bab * 64 + cb + 2 * jp;
            ull lx = *(const ull*)&g_logX[k * DD + ab];
            *(ull*)&g_Y[k * DD + ab] = fma2(lx, al, mul2(acc[i][jp], be));
        }
    }
}

// --------- matrix exp: scaling & squaring + Taylor-8 via PS (4+s mms) -----
__global__ void __launch_bounds__(256, 2) matexp_kernel(float* __restrict__ out) {
    extern __shared__ float sm[];
    float* bufA = sm;
    float* b1   = sm + D * SLD;
    float* b2   = sm + 2 * D * SLD;
    int mat = blockIdx.x, t = threadIdx.x;
    int tx = t & 15, ty = t >> 4;
    int cb = 4 * tx;
    float lq = 0.f;
#pragma unroll
    for (int q = 0; q < 16; q++) {
        int l = t + 256 * q;
        int r = l >> 6, c = l & 63;
        float v = g_Y[mat * DD + l];
        bufA[r * SLD + c] = v;
        lq += v * v;
    }
    b1[t] = lq;
    __syncthreads();
    for (int off = 128; off > 0; off >>= 1) {
        if (t < off) b1[t] += b1[t + off];
        __syncthreads();
    }
    float fro = sqrtf(b1[0]);
    __syncthreads();
    int s = 0;
    while (fro > 0.5f && s < 12) { fro *= 0.5f; s++; }
    float scale = ldexpf(1.f, -s);
#pragma unroll
    for (int q = 0; q < 16; q++) {
        int l = t + 256 * q;
        int r = l >> 6, c = l & 63;
        bufA[r * SLD + c] *= scale;
    }
    __syncthreads();

    const float cf[9] = {1.f, 1.f, 0.5f, 1.f / 6.f, 1.f / 24.f, 1.f / 120.f,
                         1.f / 720.f, 1.f / 5040.f, 1.f / 40320.f};
    ull Q0[4][2], Q1[4][2], Q2[4][2];
    {
        ull k0 = fdup(cf[0]), k1 = fdup(cf[1]);
        ull k3 = fdup(cf[3]), k4 = fdup(cf[4]);
        ull k6 = fdup(cf[6]), k7 = fdup(cf[7]);
#pragma unroll
        for (int i = 0; i < 4; i++) { int r = 4 * ty + i;
#pragma unroll
            for (int jp = 0; jp < 2; jp++) {
                ull a  = *TOFF(bufA, i, jp);
                ull dg = dgp(r, cb, jp);
                Q0[i][jp] = fma2(a, k1, mul2(dg, k0));
                Q1[i][jp] = fma2(a, k4, mul2(dg, k3));
                Q2[i][jp] = fma2(a, k7, mul2(dg, k6));
            } }
    }
    // A2 -> b1
    {
        ull acc[4][2] = {}; mmp(bufA, bufA, D, acc, tx, ty);
        ull k2 = fdup(cf[2]), k5 = fdup(cf[5]), k8 = fdup(cf[8]);
#pragma unroll
        for (int i = 0; i < 4; i++)
#pragma unroll
            for (int jp = 0; jp < 2; jp++) {
                ull v = acc[i][jp];
                *TOFF(b1, i, jp) = v;
                Q0[i][jp] = fma2(v, k2, Q0[i][jp]);
                Q1[i][jp] = fma2(v, k5, Q1[i][jp]);
                Q2[i][jp] = fma2(v, k8, Q2[i][jp]);
            }
        __syncthreads();
    }
    // A3 -> b2
    {
        ull acc[4][2] = {}; mmp(bufA, b1, D, acc, tx, ty);
#pragma unroll
        for (int i = 0; i < 4; i++)
#pragma unroll
            for (int jp = 0; jp < 2; jp++) *TOFF(b2, i, jp) = acc[i][jp];
        __syncthreads();
    }
    // dump Q2 -> b1 (A2 dead)
#pragma unroll
    for (int i = 0; i < 4; i++)
#pragma unroll
        for (int jp = 0; jp < 2; jp++) *TOFF(b1, i, jp) = Q2[i][jp];
    __syncthreads();
    // V = A3*Q2 + Q1 -> bufA
    {
        ull acc[4][2] = {}; mmp(b2, b1, D, acc, tx, ty);
#pragma unroll
        for (int i = 0; i < 4; i++)
#pragma unroll
            for (int jp = 0; jp < 2; jp++)
                *TOFF(bufA, i, jp) = add2(acc[i][jp], Q1[i][jp]);
        __syncthreads();
    }
    // R = A3*V + Q0 -> b1
    {
        ull acc[4][2] = {}; mmp(b2, bufA, D, acc, tx, ty);
#pragma unroll
        for (int i = 0; i < 4; i++)
#pragma unroll
            for (int jp = 0; jp < 2; jp++)
                *TOFF(b1, i, jp) = add2(acc[i][jp], Q0[i][jp]);
        __syncthreads();
    }
    // s squarings
    float* cur = b1; float* nxt = b2;
    for (int it = 0; it < s; it++) {
        ull acc[4][2] = {}; mmp(cur, cur, D, acc, tx, ty);
#pragma unroll
        for (int i = 0; i < 4; i++)
#pragma unroll
            for (int jp = 0; jp < 2; jp++) *TOFF(nxt, i, jp) = acc[i][jp];
        __syncthreads();
        float* tmp = cur; cur = nxt; nxt = tmp;
    }
#pragma unroll
    for (int i = 0; i < 4; i++)
#pragma unroll
        for (int jp = 0; jp < 2; jp++)
            *(ull*)&out[mat * DD + (4 * ty + i) * 64 + cb + 2 * jp] = *TOFF(cur, i, jp);
}

// ---------------- launch ---------------------------------------------------
extern "C" void kernel_launch(void* const* d_in, const int* in_sizes, int n_in,
                              void* d_out, int out_size) {
    const float* X  = (const float*)d_in[0];
    const float* bw = (const float*)d_in[1];
    for (int i = 0; i < n_in; i++) {
        if (in_sizes[i] == NMAT * DD) X = (const float*)d_in[i];
        else if (in_sizes[i] == 1)    bw = (const float*)d_in[i];
    }
    // host-side Chebyshev-PS coefficients (double precision, deterministic)
    CC cc;
    {
        double mid = 0.5 * (LOG_HI + LOG_LO), half = 0.5 * (LOG_HI - LOG_LO);
        double gam = half / mid;
        double tt = (sqrt(1.0 - gam * gam) - 1.0) / gam;
        double g[4][8];
        g[0][0] = log(mid) - log(1.0 + tt * tt);
        double tp = tt;
        for (int k = 1; k < 32; k++) { g[k >> 3][k & 7] = -2.0 * tp / (double)k; tp *= tt; }
        for (int q = 3; q >= 1; q--)
            for (int r = 1; r < 8; r++) g[q - 1][8 - r] -= g[q][r];
        for (int r = 0; r < 8; r++) cc.c[0][r] = (float)g[0][r];
        for (int q = 1; q < 4; q++) {
            cc.c[q][0] = (float)g[q][0];
            for (int r = 1; r < 8; r++) cc.c[q][r] = (float)(2.0 * g[q][r]);
        }
    }
    int smem = 3 * D * SLD * (int)sizeof(float);
    cudaFuncSetAttribute(matlog_kernel, cudaFuncAttributeMaxDynamicSharedMemorySize, smem);
    cudaFuncSetAttribute(matexp_kernel, cudaFuncAttributeMaxDynamicSharedMemorySize, smem);

    matlog_kernel<<<NMAT, 256, smem>>>(X, cc);
    gram_kernel<<<dim3(8, 8, 8), 256>>>();
    w_kernel<<<(NMAT * NMAT) / 256, 256>>>(bw);
    rowcol_kernel<<<NMAT, 256>>>();
    ygemm_kernel<<<dim3(64, 4), 256>>>();
    matexp_kernel<<<NMAT, 256, smem>>>((float*)d_out);
}